// round 9
// baseline (speedup 1.0000x reference)
#include <cuda_runtime.h>
#include <cuda_fp16.h>

#define DIM_H 512
#define DIM_W 512
#define NIMG  128
#define NROWS (NIMG * DIM_H)           // 65536 row-lines
#define INV_SCALE (1.0f / (512.0f * 512.0f))
#define PLX 580                         // float2 plane pitch: >=576, ==4 mod 16
#define WP 264                          // half-spectrum storage pitch (complex), 257 used

// Half-spectrum scratch in fp16 complex: [img][h][pw<WP], 69 MB.
__device__ __half2 g_scratch[(size_t)NIMG * DIM_H * WP];
// Baked Hermitianized filter (fp32): [pw 0..256][ph 0..511], scale+untangle folded.
__device__ float2 g_filter[(size_t)257 * DIM_H];
// Baked twiddles: g_tws[k] = exp(-2*pi*i*k/512), k in [0,64)
__device__ float2 g_tws[64];

__device__ __forceinline__ float2 cadd(float2 a, float2 b){ return make_float2(a.x+b.x, a.y+b.y); }
__device__ __forceinline__ float2 csub(float2 a, float2 b){ return make_float2(a.x-b.x, a.y-b.y); }
__device__ __forceinline__ float2 cmul(float2 a, float2 b){
    return make_float2(a.x*b.x - a.y*b.y, a.x*b.y + a.y*b.x);
}
__device__ __forceinline__ float2 cconj(float2 a){ return make_float2(a.x, -a.y); }

__device__ __forceinline__ __half2 pack_h2(float re, float im){ return __floats2half2_rn(re, im); }
__device__ __forceinline__ float2 unpack_h2(__half2 v){ return __half22float2(v); }

// storage-position <-> frequency permutation: swap low two octal digits (involution, keeps bit 8)
__device__ __forceinline__ int kmap9(int p){
    return (p & 448) | ((p & 7) << 3) | ((p >> 3) & 7);
}

// NB=true: named 2-warp barrier (64 threads, id = bid). NB=false: block-wide.
template<bool NB>
__device__ __forceinline__ void barsync(int bid){
    if (NB) asm volatile("bar.sync %0, 64;" :: "r"(bid) : "memory");
    else    __syncthreads();
}

// 8-point DFT, natural in/out: out[r] = sum_j in[j] * exp(S*2*pi*i*j*r/8)
template<int S>
__device__ __forceinline__ void dft8(float2* a){
    const float sg = (float)S;
    float2 e0=a[0], e1=a[2], e2=a[4], e3=a[6];
    float2 o0=a[1], o1=a[3], o2=a[5], o3=a[7];
    float2 t0=cadd(e0,e2), t1=csub(e0,e2), t2=cadd(e1,e3), t3=csub(e1,e3);
    float2 t3r = make_float2(-sg*t3.y, sg*t3.x);
    float2 E0=cadd(t0,t2), E2=csub(t0,t2), E1=cadd(t1,t3r), E3=csub(t1,t3r);
    float2 u0=cadd(o0,o2), u1=csub(o0,o2), u2=cadd(o1,o3), u3=csub(o1,o3);
    float2 u3r = make_float2(-sg*u3.y, sg*u3.x);
    float2 O0=cadd(u0,u2), O2=csub(u0,u2), O1=cadd(u1,u3r), O3=csub(u1,u3r);
    const float c = 0.70710678118654752f;
    O1 = make_float2(c*(O1.x - sg*O1.y), c*(sg*O1.x + O1.y));
    O2 = make_float2(-sg*O2.y, sg*O2.x);
    O3 = make_float2(c*(-O3.x - sg*O3.y), c*(sg*O3.x - O3.y));
    a[0]=cadd(E0,O0); a[4]=csub(E0,O0);
    a[1]=cadd(E1,O1); a[5]=csub(E1,O1);
    a[2]=cadd(E2,O2); a[6]=csub(E2,O2);
    a[3]=cadd(E3,O3); a[7]=csub(E3,O3);
}

// Apply w^r to a[r], r=1..7, via binary powering (dep depth 3).
__device__ __forceinline__ void apply7(float2* a, float2 w1){
    float2 w2 = cmul(w1, w1);
    float2 w3 = cmul(w2, w1);
    float2 w4 = cmul(w2, w2);
    float2 w5 = cmul(w3, w2);
    float2 w6 = cmul(w3, w3);
    float2 w7 = cmul(w4, w3);
    a[1] = cmul(a[1], w1); a[2] = cmul(a[2], w2); a[3] = cmul(a[3], w3);
    a[4] = cmul(a[4], w4); a[5] = cmul(a[5], w5); a[6] = cmul(a[6], w6);
    a[7] = cmul(a[7], w7);
}

// Forward 512-pt FFT. In: a[j] = x[t + 64*j]. Out: a[q] = X[kmap9(t + 64*q)].
template<bool NB>
__device__ __forceinline__ void fft512_fwd(float2* a, float2* plane, int t,
                                           const float2* tws, int bid){
    dft8<-1>(a);
    apply7(a, tws[t]);
    #pragma unroll
    for (int r = 0; r < 8; ++r) plane[r*72 + t] = a[r];
    barsync<NB>(bid);
    int tp = t & 7, rr = t >> 3;
    #pragma unroll
    for (int j = 0; j < 8; ++j) a[j] = plane[rr*72 + tp + 8*j];
    dft8<-1>(a);
    apply7(a, tws[tp*8]);
    barsync<NB>(bid);
    #pragma unroll
    for (int r1 = 0; r1 < 8; ++r1) plane[rr*72 + r1*9 + tp] = a[r1];
    barsync<NB>(bid);
    #pragma unroll
    for (int k = 0; k < 8; ++k) a[k] = plane[t*9 + k];
    dft8<-1>(a);
}

// Inverse (unscaled) 512-pt FFT. In: a[q] = S[kmap9(t + 64*q)]. Out: a[j] = y[t + 64*j].
template<bool NB>
__device__ __forceinline__ void fft512_inv(float2* a, float2* plane, int t,
                                           const float2* tws, int bid){
    dft8<1>(a);
    int tp = t & 7, rr = t >> 3;
    #pragma unroll
    for (int k = 0; k < 8; ++k) plane[t*9 + k] = a[k];
    barsync<NB>(bid);
    #pragma unroll
    for (int r1 = 0; r1 < 8; ++r1) a[r1] = plane[rr*72 + r1*9 + tp];
    apply7(a, cconj(tws[tp*8]));
    dft8<1>(a);
    barsync<NB>(bid);
    #pragma unroll
    for (int j = 0; j < 8; ++j) plane[rr*72 + tp + 8*j] = a[j];
    barsync<NB>(bid);
    #pragma unroll
    for (int r = 0; r < 8; ++r) a[r] = plane[r*72 + t];
    apply7(a, cconj(tws[t]));
    dft8<1>(a);
}

// ---------------------------------------------------------------------------
// Kernel 0: bake Hermitianized filter + twiddle table.
// Filter = 0.25 * (H[s0] + conj(H[s1])) * INV_SCALE
// ---------------------------------------------------------------------------
__global__ void k_bake_filter(const float* __restrict__ Hr, const float* __restrict__ Hi){
    int pw = blockIdx.x;          // 0..256
    int ph = threadIdx.x;         // 0..511
    if (pw == 0 && ph < 64){
        float s, c;
        sincosf(-6.283185307179586f * (float)ph / 512.0f, &s, &c);
        g_tws[ph] = make_float2(c, s);
    }
    int kh = kmap9(ph), kw = kmap9(pw);
    int nh = (512 - kh) & 511, nw = (512 - kw) & 511;
    int s0 = kh * 512 + kw;
    int s1 = nh * 512 + nw;
    float re = 0.25f * (Hr[s0] + Hr[s1]);
    float im = 0.25f * (Hi[s0] - Hi[s1]);
    g_filter[pw * 512 + ph] = make_float2(re * INV_SCALE, im * INV_SCALE);
}

// ---------------------------------------------------------------------------
// Kernel 1: paired forward FFT along W. 64 threads = one FFT pair per block.
// ---------------------------------------------------------------------------
__global__ void __launch_bounds__(64) k_fft_rows(const float* __restrict__ x){
    __shared__ float2 sD[PLX];
    __shared__ float2 tws[64];
    int t = threadIdx.x;
    tws[t] = g_tws[t];
    long long pair = blockIdx.x;
    const float* x0 = x + pair * 1024;
    const float* x1 = x0 + 512;

    float2 a[8];
    #pragma unroll
    for (int j = 0; j < 8; ++j) a[j] = make_float2(x0[t + 64*j], x1[t + 64*j]);
    __syncthreads();   // tws ready

    fft512_fwd<false>(a, sD, t, tws, 0);

    __syncthreads();
    #pragma unroll
    for (int q = 0; q < 8; ++q) sD[t + 64*q] = a[q];
    __syncthreads();

    __half2* g0 = g_scratch + (pair * 2) * WP;
    __half2* g1 = g0 + WP;
    #pragma unroll
    for (int q = 0; q < 4; ++q){
        int p = t + 64*q;
        int pm = p ? kmap9(512 - kmap9(p)) : 0;
        float2 A = sD[p];
        float2 B = sD[pm];
        g0[p] = pack_h2(A.x + B.x, A.y - B.y);
        g1[p] = pack_h2(A.y + B.y, B.x - A.x);
    }
    if (t == 0){   // p = 256, self-mirror
        float2 A = sD[256];
        g0[256] = pack_h2(2.0f * A.x, 0.0f);
        g1[256] = pack_h2(2.0f * A.y, 0.0f);
    }
}

// ---------------------------------------------------------------------------
// Kernel 2: per image, 8 columns of the half spectrum (full-sector fp16 I/O):
// fwd col FFT -> Heff multiply -> inv col FFT. Named 64-thread barriers per line.
// ---------------------------------------------------------------------------
__global__ void __launch_bounds__(512) k_cols(void){
    __shared__ float2 sD[8][PLX];
    __shared__ float2 tws[64];
    int tid = threadIdx.x;
    if (tid < 64) tws[tid] = g_tws[tid];

    int img = blockIdx.x / 33;
    int w0  = (blockIdx.x % 33) << 3;
    __half2* base = g_scratch + (long long)img * DIM_H * WP;

    #pragma unroll
    for (int it = 0; it < 8; ++it){
        int idx = it * 512 + tid;
        int wi = idx & 7, h = idx >> 3;
        int wc = w0 + wi; if (wc > 256) wc = 256;
        sD[wi][h] = unpack_h2(base[(long long)h * WP + wc]);
    }
    __syncthreads();   // cross-plane staging + tws

    int line = tid >> 6, t = tid & 63;
    int bid = 1 + line;
    float2 a[8];
    #pragma unroll
    for (int j = 0; j < 8; ++j) a[j] = sD[line][t + 64*j];
    barsync<true>(bid);   // own-plane staging reads done before fwd writes

    fft512_fwd<true>(a, sD[line], t, tws, bid);

    int pwcol = w0 + line; if (pwcol > 256) pwcol = 256;
    const float2* frow = g_filter + (long long)pwcol * 512 + t;
    #pragma unroll
    for (int q = 0; q < 8; ++q) a[q] = cmul(a[q], frow[64*q]);

    barsync<true>(bid);   // fwd's last plane reads done before inv writes

    fft512_inv<true>(a, sD[line], t, tws, bid);

    barsync<true>(bid);   // inv's last plane reads done before staging writes
    #pragma unroll
    for (int j = 0; j < 8; ++j) sD[line][t + 64*j] = a[j];
    __syncthreads();      // cross-plane staging out

    #pragma unroll
    for (int it = 0; it < 8; ++it){
        int idx = it * 512 + tid;
        int wi = idx & 7, h = idx >> 3;
        if (w0 + wi <= 256){
            float2 v = sD[wi][h];
            base[(long long)h * WP + w0 + wi] = pack_h2(v.x, v.y);
        }
    }
}

// ---------------------------------------------------------------------------
// Kernel 3: paired inverse FFT along W (C2R x2). 64 threads = one pair per block.
// ---------------------------------------------------------------------------
__global__ void __launch_bounds__(64) k_ifft_rows(float* __restrict__ out){
    __shared__ float2 sD[PLX];
    __shared__ float2 tws[64];
    int t = threadIdx.x;
    tws[t] = g_tws[t];
    long long pair = blockIdx.x;
    const __half2* g0 = g_scratch + (pair * 2) * WP;
    const __half2* g1 = g0 + WP;

    // stage both half-spectra: S0 at [0..256], S1 at [288..544]
    #pragma unroll
    for (int j = 0; j < 4; ++j){
        int p = t + 64*j;
        sD[p]       = unpack_h2(g0[p]);
        sD[288 + p] = unpack_h2(g1[p]);
    }
    if (t == 0){
        sD[256]       = unpack_h2(g0[256]);
        sD[288 + 256] = unpack_h2(g1[256]);
    }
    __syncthreads();

    // build permuted Z in registers:
    // p<=256: Z = S0[p] + i*S1[p];  p>256: Z = conj(S0[ps]) + i*conj(S1[ps])
    float2 a[8];
    #pragma unroll
    for (int q = 0; q < 8; ++q){
        int p = t + 64*q;
        if (p <= 256){
            float2 A = sD[p];
            float2 B = sD[288 + p];
            a[q] = make_float2(A.x - B.y, A.y + B.x);
        } else {
            int ps = kmap9(512 - kmap9(p));   // in [1,255]
            float2 A = sD[ps];
            float2 B = sD[288 + ps];
            a[q] = make_float2(A.x + B.y, B.x - A.y);
        }
    }
    __syncthreads();   // staging reads done before inv FFT reuses plane

    fft512_inv<false>(a, sD, t, tws, 0);

    float* o0 = out + (pair * 2) * 512;
    float* o1 = o0 + 512;
    #pragma unroll
    for (int j = 0; j < 8; ++j){
        o0[t + 64*j] = a[j].x;
        o1[t + 64*j] = a[j].y;
    }
}

// ---------------------------------------------------------------------------
extern "C" void kernel_launch(void* const* d_in, const int* in_sizes, int n_in,
                              void* d_out, int out_size){
    const float* x  = (const float*)d_in[0];
    const float* Hr = (const float*)d_in[1];
    const float* Hi = (const float*)d_in[2];
    float* out = (float*)d_out;

    k_bake_filter<<<257, 512>>>(Hr, Hi);
    k_fft_rows<<<NROWS / 2, 64>>>(x);
    k_cols<<<NIMG * 33, 512>>>();
    k_ifft_rows<<<NROWS / 2, 64>>>(out);
}

// round 10
// speedup vs baseline: 1.0845x; 1.0845x over previous
#include <cuda_runtime.h>
#include <cuda_fp16.h>

#define DIM_H 512
#define NIMG  128
#define NROWS (NIMG * DIM_H)           // 65536 row-lines
#define INV_SCALE (1.0f / (512.0f * 512.0f))
#define PLX 580                         // float2 plane pitch
#define NGRP 33                         // column groups of 8 (257 cols padded to 264)
#define GRP  4096                       // half2 per group = 512*8
#define IMGS (NGRP * GRP)               // half2 per image = 135168

// Scratch: [img][group][h][wi] in fp16 complex, 69 MB. Group = 8 adjacent spectrum cols.
__device__ __half2 g_scratch[(size_t)NIMG * IMGS];
// Baked Hermitianized filter (fp32): [pw 0..256][ph 0..511], scale+untangle folded.
__device__ float2 g_filter[(size_t)257 * 512];
// Baked twiddles: g_tws[k] = exp(-2*pi*i*k/512), k in [0,64)
__device__ float2 g_tws[64];

__device__ __forceinline__ float2 cadd(float2 a, float2 b){ return make_float2(a.x+b.x, a.y+b.y); }
__device__ __forceinline__ float2 csub(float2 a, float2 b){ return make_float2(a.x-b.x, a.y-b.y); }
__device__ __forceinline__ float2 cmul(float2 a, float2 b){
    return make_float2(a.x*b.x - a.y*b.y, a.x*b.y + a.y*b.x);
}
__device__ __forceinline__ float2 cconj(float2 a){ return make_float2(a.x, -a.y); }

__device__ __forceinline__ __half2 pack_h2(float re, float im){ return __floats2half2_rn(re, im); }
__device__ __forceinline__ float2 unpack_h2(__half2 v){ return __half22float2(v); }
__device__ __forceinline__ float2 unpack_u(unsigned u){
    __half2 h = *reinterpret_cast<__half2*>(&u);
    return __half22float2(h);
}
__device__ __forceinline__ unsigned pack_u(float x, float y){
    __half2 h = __floats2half2_rn(x, y);
    return *reinterpret_cast<unsigned*>(&h);
}

// storage-position <-> frequency permutation: swap low two octal digits (involution, keeps bit 8)
__device__ __forceinline__ int kmap9(int p){
    return (p & 448) | ((p & 7) << 3) | ((p >> 3) & 7);
}

// 8-point DFT, natural in/out: out[r] = sum_j in[j] * exp(S*2*pi*i*j*r/8)
template<int S>
__device__ __forceinline__ void dft8(float2* a){
    const float sg = (float)S;
    float2 e0=a[0], e1=a[2], e2=a[4], e3=a[6];
    float2 o0=a[1], o1=a[3], o2=a[5], o3=a[7];
    float2 t0=cadd(e0,e2), t1=csub(e0,e2), t2=cadd(e1,e3), t3=csub(e1,e3);
    float2 t3r = make_float2(-sg*t3.y, sg*t3.x);
    float2 E0=cadd(t0,t2), E2=csub(t0,t2), E1=cadd(t1,t3r), E3=csub(t1,t3r);
    float2 u0=cadd(o0,o2), u1=csub(o0,o2), u2=cadd(o1,o3), u3=csub(o1,o3);
    float2 u3r = make_float2(-sg*u3.y, sg*u3.x);
    float2 O0=cadd(u0,u2), O2=csub(u0,u2), O1=cadd(u1,u3r), O3=csub(u1,u3r);
    const float c = 0.70710678118654752f;
    O1 = make_float2(c*(O1.x - sg*O1.y), c*(sg*O1.x + O1.y));
    O2 = make_float2(-sg*O2.y, sg*O2.x);
    O3 = make_float2(c*(-O3.x - sg*O3.y), c*(sg*O3.x - O3.y));
    a[0]=cadd(E0,O0); a[4]=csub(E0,O0);
    a[1]=cadd(E1,O1); a[5]=csub(E1,O1);
    a[2]=cadd(E2,O2); a[6]=csub(E2,O2);
    a[3]=cadd(E3,O3); a[7]=csub(E3,O3);
}

// Apply w^r to a[r], r=1..7, via binary powering (dep depth 3).
__device__ __forceinline__ void apply7(float2* a, float2 w1){
    float2 w2 = cmul(w1, w1);
    float2 w3 = cmul(w2, w1);
    float2 w4 = cmul(w2, w2);
    float2 w5 = cmul(w3, w2);
    float2 w6 = cmul(w3, w3);
    float2 w7 = cmul(w4, w3);
    a[1] = cmul(a[1], w1); a[2] = cmul(a[2], w2); a[3] = cmul(a[3], w3);
    a[4] = cmul(a[4], w4); a[5] = cmul(a[5], w5); a[6] = cmul(a[6], w6);
    a[7] = cmul(a[7], w7);
}

// Forward 512-pt FFT. In: a[j] = x[t + 64*j]. Out: a[q] = X[kmap9(t + 64*q)].
__device__ __forceinline__ void fft512_fwd(float2* a, float2* plane, int t,
                                           const float2* tws){
    dft8<-1>(a);
    apply7(a, tws[t]);
    #pragma unroll
    for (int r = 0; r < 8; ++r) plane[r*72 + t] = a[r];
    __syncthreads();
    int tp = t & 7, rr = t >> 3;
    #pragma unroll
    for (int j = 0; j < 8; ++j) a[j] = plane[rr*72 + tp + 8*j];
    dft8<-1>(a);
    apply7(a, tws[tp*8]);
    __syncthreads();
    #pragma unroll
    for (int r1 = 0; r1 < 8; ++r1) plane[rr*72 + r1*9 + tp] = a[r1];
    __syncthreads();
    #pragma unroll
    for (int k = 0; k < 8; ++k) a[k] = plane[t*9 + k];
    dft8<-1>(a);
}

// Inverse (unscaled) 512-pt FFT. In: a[q] = S[kmap9(t + 64*q)]. Out: a[j] = y[t + 64*j].
__device__ __forceinline__ void fft512_inv(float2* a, float2* plane, int t,
                                           const float2* tws){
    dft8<1>(a);
    int tp = t & 7, rr = t >> 3;
    #pragma unroll
    for (int k = 0; k < 8; ++k) plane[t*9 + k] = a[k];
    __syncthreads();
    #pragma unroll
    for (int r1 = 0; r1 < 8; ++r1) a[r1] = plane[rr*72 + r1*9 + tp];
    apply7(a, cconj(tws[tp*8]));
    dft8<1>(a);
    __syncthreads();
    #pragma unroll
    for (int j = 0; j < 8; ++j) plane[rr*72 + tp + 8*j] = a[j];
    __syncthreads();
    #pragma unroll
    for (int r = 0; r < 8; ++r) a[r] = plane[r*72 + t];
    apply7(a, cconj(tws[t]));
    dft8<1>(a);
}

// ---------------------------------------------------------------------------
// Kernel 0: bake Hermitianized filter + twiddle table.
// Filter = 0.25 * (H[s0] + conj(H[s1])) * INV_SCALE
// ---------------------------------------------------------------------------
__global__ void k_bake_filter(const float* __restrict__ Hr, const float* __restrict__ Hi){
    int pw = blockIdx.x;          // 0..256
    int ph = threadIdx.x;         // 0..511
    if (pw == 0 && ph < 64){
        float s, c;
        sincosf(-6.283185307179586f * (float)ph / 512.0f, &s, &c);
        g_tws[ph] = make_float2(c, s);
    }
    int kh = kmap9(ph), kw = kmap9(pw);
    int nh = (512 - kh) & 511, nw = (512 - kw) & 511;
    int s0 = kh * 512 + kw;
    int s1 = nh * 512 + nw;
    float re = 0.25f * (Hr[s0] + Hr[s1]);
    float im = 0.25f * (Hi[s0] - Hi[s1]);
    g_filter[pw * 512 + ph] = make_float2(re * INV_SCALE, im * INV_SCALE);
}

// ---------------------------------------------------------------------------
// Kernel 1: paired forward FFT along W. 64 threads = one FFT pair per block.
// Writes half-spectra into grouped layout: idx = (p>>3)*GRP + h*8 + (p&7).
// ---------------------------------------------------------------------------
__global__ void __launch_bounds__(64) k_fft_rows(const float* __restrict__ x){
    __shared__ float2 sD[PLX];
    __shared__ float2 tws[64];
    int t = threadIdx.x;
    tws[t] = g_tws[t];
    int pair = blockIdx.x;               // 0..32767
    int img  = pair >> 8;
    int h0   = (pair & 255) * 2;
    const float* x0 = x + (size_t)pair * 1024;
    const float* x1 = x0 + 512;

    float2 a[8];
    #pragma unroll
    for (int j = 0; j < 8; ++j) a[j] = make_float2(x0[t + 64*j], x1[t + 64*j]);
    __syncthreads();   // tws ready

    fft512_fwd(a, sD, t, tws);

    __syncthreads();
    #pragma unroll
    for (int q = 0; q < 8; ++q) sD[t + 64*q] = a[q];
    __syncthreads();

    __half2* ib = g_scratch + (size_t)img * IMGS;
    int rr = t >> 3, tp = t & 7;
    #pragma unroll
    for (int q = 0; q < 4; ++q){
        int p = t + 64*q;
        int pm = p ? kmap9(512 - kmap9(p)) : 0;
        float2 A = sD[p];
        float2 B = sD[pm];
        unsigned off = (unsigned)(8*q + rr) * GRP + tp;
        ib[off + h0*8]       = pack_h2(A.x + B.x, A.y - B.y);
        ib[off + (h0+1)*8]   = pack_h2(A.y + B.y, B.x - A.x);
    }
    if (t == 0){   // p = 256, self-mirror: group 32, wi 0
        float2 A = sD[256];
        unsigned off = 32u * GRP;
        ib[off + h0*8]     = pack_h2(2.0f * A.x, 0.0f);
        ib[off + (h0+1)*8] = pack_h2(2.0f * A.y, 0.0f);
    }
}

// ---------------------------------------------------------------------------
// Kernel 2: per image, one group of 8 spectrum columns per block (256 thr).
// Contiguous 16KB uint4 stage-in/out; each 64-thread line runs 2 columns.
// ---------------------------------------------------------------------------
#define SHP 513   // uint pitch per column in staging buffer (conflict-free)
__global__ void __launch_bounds__(256) k_cols(void){
    __shared__ float2 sD[4][PLX];
    __shared__ unsigned sH[8 * SHP];
    __shared__ float2 tws[64];
    int tid = threadIdx.x;
    if (tid < 64) tws[tid] = g_tws[tid];

    int img = blockIdx.x / NGRP;
    int g   = blockIdx.x % NGRP;
    uint4* gbase = (uint4*)(g_scratch + (size_t)img * IMGS + (size_t)g * GRP);

    // stage-in: 1024 uint4 = 4096 half2 (full group), perfectly coalesced
    #pragma unroll
    for (int it = 0; it < 4; ++it){
        int idx = it * 256 + tid;        // 0..1023
        uint4 v = gbase[idx];
        int h  = idx >> 1;
        int wb = (idx & 1) * 4;
        sH[(wb+0)*SHP + h] = v.x;
        sH[(wb+1)*SHP + h] = v.y;
        sH[(wb+2)*SHP + h] = v.z;
        sH[(wb+3)*SHP + h] = v.w;
    }
    __syncthreads();

    int line = tid >> 6, t = tid & 63;
    #pragma unroll
    for (int half = 0; half < 2; ++half){
        int wi = line + half * 4;
        float2 a[8];
        #pragma unroll
        for (int j = 0; j < 8; ++j) a[j] = unpack_u(sH[wi*SHP + t + 64*j]);

        fft512_fwd(a, sD[line], t, tws);   // first plane write is safe: prior
                                           // sync (stage-in / end of half 0)

        int pw = g * 8 + wi; if (pw > 256) pw = 256;
        const float2* frow = g_filter + (size_t)pw * 512 + t;
        #pragma unroll
        for (int q = 0; q < 8; ++q) a[q] = cmul(a[q], frow[64*q]);

        __syncthreads();   // fwd's last plane reads done before inv writes

        fft512_inv(a, sD[line], t, tws);

        __syncthreads();   // inv's last plane reads done before next fwd / exit
        #pragma unroll
        for (int j = 0; j < 8; ++j) sH[wi*SHP + t + 64*j] = pack_u(a[j].x, a[j].y);
    }
    __syncthreads();

    // stage-out
    #pragma unroll
    for (int it = 0; it < 4; ++it){
        int idx = it * 256 + tid;
        int h  = idx >> 1;
        int wb = (idx & 1) * 4;
        uint4 v;
        v.x = sH[(wb+0)*SHP + h];
        v.y = sH[(wb+1)*SHP + h];
        v.z = sH[(wb+2)*SHP + h];
        v.w = sH[(wb+3)*SHP + h];
        gbase[idx] = v;
    }
}

// ---------------------------------------------------------------------------
// Kernel 3: paired inverse FFT along W (C2R x2). 64 threads = one pair per block.
// ---------------------------------------------------------------------------
__global__ void __launch_bounds__(64) k_ifft_rows(float* __restrict__ out){
    __shared__ float2 sD[PLX];
    __shared__ float2 tws[64];
    int t = threadIdx.x;
    tws[t] = g_tws[t];
    int pair = blockIdx.x;
    int img  = pair >> 8;
    int h0   = (pair & 255) * 2;
    const __half2* ib = g_scratch + (size_t)img * IMGS;
    int rr = t >> 3, tp = t & 7;

    // stage both half-spectra: S0 at [0..256], S1 at [288..544]
    #pragma unroll
    for (int j = 0; j < 4; ++j){
        int p = t + 64*j;
        unsigned off = (unsigned)(8*j + rr) * GRP + tp;
        sD[p]       = unpack_h2(ib[off + h0*8]);
        sD[288 + p] = unpack_h2(ib[off + (h0+1)*8]);
    }
    if (t == 0){
        unsigned off = 32u * GRP;
        sD[256]       = unpack_h2(ib[off + h0*8]);
        sD[288 + 256] = unpack_h2(ib[off + (h0+1)*8]);
    }
    __syncthreads();

    // build permuted Z in registers:
    // p<=256: Z = S0[p] + i*S1[p];  p>256: Z = conj(S0[ps]) + i*conj(S1[ps])
    float2 a[8];
    #pragma unroll
    for (int q = 0; q < 8; ++q){
        int p = t + 64*q;
        if (p <= 256){
            float2 A = sD[p];
            float2 B = sD[288 + p];
            a[q] = make_float2(A.x - B.y, A.y + B.x);
        } else {
            int ps = kmap9(512 - kmap9(p));   // in [1,255]
            float2 A = sD[ps];
            float2 B = sD[288 + ps];
            a[q] = make_float2(A.x + B.y, B.x - A.y);
        }
    }
    __syncthreads();   // staging reads done before inv FFT reuses plane

    fft512_inv(a, sD, t, tws);

    float* o0 = out + (size_t)pair * 1024;
    float* o1 = o0 + 512;
    #pragma unroll
    for (int j = 0; j < 8; ++j){
        o0[t + 64*j] = a[j].x;
        o1[t + 64*j] = a[j].y;
    }
}

// ---------------------------------------------------------------------------
extern "C" void kernel_launch(void* const* d_in, const int* in_sizes, int n_in,
                              void* d_out, int out_size){
    const float* x  = (const float*)d_in[0];
    const float* Hr = (const float*)d_in[1];
    const float* Hi = (const float*)d_in[2];
    float* out = (float*)d_out;

    k_bake_filter<<<257, 512>>>(Hr, Hi);
    k_fft_rows<<<NROWS / 2, 64>>>(x);
    k_cols<<<NIMG * NGRP, 256>>>();
    k_ifft_rows<<<NROWS / 2, 64>>>(out);
}

// round 11
// speedup vs baseline: 1.1015x; 1.0156x over previous
#include <cuda_runtime.h>
#include <cuda_fp16.h>

#define DIM_H 512
#define NIMG  128
#define NROWS (NIMG * DIM_H)           // 65536 row-lines
#define INV_SCALE (1.0f / (512.0f * 512.0f))
#define PLX 580                         // float2 plane pitch (row kernels)
#define HPL 584                         // half2 plane pitch (cols)
#define NGRP 33                         // column groups of 8 (257 cols padded to 264)
#define GRP  4096                       // half2 per group = 512*8
#define IMGS (NGRP * GRP)               // half2 per image = 135168

// Scratch: [img][group][h][wi] in fp16 complex, 69 MB. Group = 8 adjacent spectrum cols.
__device__ __half2 g_scratch[(size_t)NIMG * IMGS];
// Baked Hermitianized filter (fp32): [pw 0..256][ph 0..511], scale+untangle folded.
__device__ float2 g_filter[(size_t)257 * 512];
// Baked twiddles: g_tws[k] = exp(-2*pi*i*k/512), k in [0,64)
__device__ float2 g_tws[64];

__device__ __forceinline__ float2 cadd(float2 a, float2 b){ return make_float2(a.x+b.x, a.y+b.y); }
__device__ __forceinline__ float2 csub(float2 a, float2 b){ return make_float2(a.x-b.x, a.y-b.y); }
__device__ __forceinline__ float2 cmul(float2 a, float2 b){
    return make_float2(a.x*b.x - a.y*b.y, a.x*b.y + a.y*b.x);
}
__device__ __forceinline__ float2 cconj(float2 a){ return make_float2(a.x, -a.y); }

__device__ __forceinline__ __half2 pack_h2(float re, float im){ return __floats2half2_rn(re, im); }
__device__ __forceinline__ float2 unpack_h2(__half2 v){ return __half22float2(v); }
__device__ __forceinline__ float2 unpack_u(unsigned u){
    __half2 h = *reinterpret_cast<__half2*>(&u);
    return __half22float2(h);
}
__device__ __forceinline__ unsigned pack_u(float x, float y){
    __half2 h = __floats2half2_rn(x, y);
    return *reinterpret_cast<unsigned*>(&h);
}

// storage-position <-> frequency permutation: swap low two octal digits (involution, keeps bit 8)
__device__ __forceinline__ int kmap9(int p){
    return (p & 448) | ((p & 7) << 3) | ((p >> 3) & 7);
}

// 8-point DFT, natural in/out: out[r] = sum_j in[j] * exp(S*2*pi*i*j*r/8)
template<int S>
__device__ __forceinline__ void dft8(float2* a){
    const float sg = (float)S;
    float2 e0=a[0], e1=a[2], e2=a[4], e3=a[6];
    float2 o0=a[1], o1=a[3], o2=a[5], o3=a[7];
    float2 t0=cadd(e0,e2), t1=csub(e0,e2), t2=cadd(e1,e3), t3=csub(e1,e3);
    float2 t3r = make_float2(-sg*t3.y, sg*t3.x);
    float2 E0=cadd(t0,t2), E2=csub(t0,t2), E1=cadd(t1,t3r), E3=csub(t1,t3r);
    float2 u0=cadd(o0,o2), u1=csub(o0,o2), u2=cadd(o1,o3), u3=csub(o1,o3);
    float2 u3r = make_float2(-sg*u3.y, sg*u3.x);
    float2 O0=cadd(u0,u2), O2=csub(u0,u2), O1=cadd(u1,u3r), O3=csub(u1,u3r);
    const float c = 0.70710678118654752f;
    O1 = make_float2(c*(O1.x - sg*O1.y), c*(sg*O1.x + O1.y));
    O2 = make_float2(-sg*O2.y, sg*O2.x);
    O3 = make_float2(c*(-O3.x - sg*O3.y), c*(sg*O3.x - O3.y));
    a[0]=cadd(E0,O0); a[4]=csub(E0,O0);
    a[1]=cadd(E1,O1); a[5]=csub(E1,O1);
    a[2]=cadd(E2,O2); a[6]=csub(E2,O2);
    a[3]=cadd(E3,O3); a[7]=csub(E3,O3);
}

// Apply w^r to a[r], r=1..7, via binary powering (dep depth 3).
__device__ __forceinline__ void apply7(float2* a, float2 w1){
    float2 w2 = cmul(w1, w1);
    float2 w3 = cmul(w2, w1);
    float2 w4 = cmul(w2, w2);
    float2 w5 = cmul(w3, w2);
    float2 w6 = cmul(w3, w3);
    float2 w7 = cmul(w4, w3);
    a[1] = cmul(a[1], w1); a[2] = cmul(a[2], w2); a[3] = cmul(a[3], w3);
    a[4] = cmul(a[4], w4); a[5] = cmul(a[5], w5); a[6] = cmul(a[6], w6);
    a[7] = cmul(a[7], w7);
}

// ---------- fp32-plane FFTs (row kernels) ----------
__device__ __forceinline__ void fft512_fwd(float2* a, float2* plane, int t,
                                           const float2* tws){
    dft8<-1>(a);
    apply7(a, tws[t]);
    #pragma unroll
    for (int r = 0; r < 8; ++r) plane[r*72 + t] = a[r];
    __syncthreads();
    int tp = t & 7, rr = t >> 3;
    #pragma unroll
    for (int j = 0; j < 8; ++j) a[j] = plane[rr*72 + tp + 8*j];
    dft8<-1>(a);
    apply7(a, tws[tp*8]);
    __syncthreads();
    #pragma unroll
    for (int r1 = 0; r1 < 8; ++r1) plane[rr*72 + r1*9 + tp] = a[r1];
    __syncthreads();
    #pragma unroll
    for (int k = 0; k < 8; ++k) a[k] = plane[t*9 + k];
    dft8<-1>(a);
}

__device__ __forceinline__ void fft512_inv(float2* a, float2* plane, int t,
                                           const float2* tws){
    dft8<1>(a);
    int tp = t & 7, rr = t >> 3;
    #pragma unroll
    for (int k = 0; k < 8; ++k) plane[t*9 + k] = a[k];
    __syncthreads();
    #pragma unroll
    for (int r1 = 0; r1 < 8; ++r1) a[r1] = plane[rr*72 + r1*9 + tp];
    apply7(a, cconj(tws[tp*8]));
    dft8<1>(a);
    __syncthreads();
    #pragma unroll
    for (int j = 0; j < 8; ++j) plane[rr*72 + tp + 8*j] = a[j];
    __syncthreads();
    #pragma unroll
    for (int r = 0; r < 8; ++r) a[r] = plane[r*72 + t];
    apply7(a, cconj(tws[t]));
    dft8<1>(a);
}

// ---------- fp16-plane FFTs (cols kernel: half the crossbar bytes) ----------
__device__ __forceinline__ void fft512_fwd_h(float2* a, __half2* pl, int t,
                                             const float2* tws){
    dft8<-1>(a);
    apply7(a, tws[t]);
    #pragma unroll
    for (int r = 0; r < 8; ++r) pl[r*72 + t] = pack_h2(a[r].x, a[r].y);
    __syncthreads();
    int tp = t & 7, rr = t >> 3;
    #pragma unroll
    for (int j = 0; j < 8; ++j) a[j] = unpack_h2(pl[rr*72 + tp + 8*j]);
    dft8<-1>(a);
    apply7(a, tws[tp*8]);
    __syncthreads();
    #pragma unroll
    for (int r1 = 0; r1 < 8; ++r1) pl[rr*72 + r1*9 + tp] = pack_h2(a[r1].x, a[r1].y);
    __syncthreads();
    #pragma unroll
    for (int k = 0; k < 8; ++k) a[k] = unpack_h2(pl[t*9 + k]);
    dft8<-1>(a);
}

__device__ __forceinline__ void fft512_inv_h(float2* a, __half2* pl, int t,
                                             const float2* tws){
    dft8<1>(a);
    int tp = t & 7, rr = t >> 3;
    #pragma unroll
    for (int k = 0; k < 8; ++k) pl[t*9 + k] = pack_h2(a[k].x, a[k].y);
    __syncthreads();
    #pragma unroll
    for (int r1 = 0; r1 < 8; ++r1) a[r1] = unpack_h2(pl[rr*72 + r1*9 + tp]);
    apply7(a, cconj(tws[tp*8]));
    dft8<1>(a);
    __syncthreads();
    #pragma unroll
    for (int j = 0; j < 8; ++j) pl[rr*72 + tp + 8*j] = pack_h2(a[j].x, a[j].y);
    __syncthreads();
    #pragma unroll
    for (int r = 0; r < 8; ++r) a[r] = unpack_h2(pl[r*72 + t]);
    apply7(a, cconj(tws[t]));
    dft8<1>(a);
}

// ---------------------------------------------------------------------------
// Kernel 0: bake Hermitianized filter + twiddle table.
// ---------------------------------------------------------------------------
__global__ void k_bake_filter(const float* __restrict__ Hr, const float* __restrict__ Hi){
    int pw = blockIdx.x;          // 0..256
    int ph = threadIdx.x;         // 0..511
    if (pw == 0 && ph < 64){
        float s, c;
        sincosf(-6.283185307179586f * (float)ph / 512.0f, &s, &c);
        g_tws[ph] = make_float2(c, s);
    }
    int kh = kmap9(ph), kw = kmap9(pw);
    int nh = (512 - kh) & 511, nw = (512 - kw) & 511;
    int s0 = kh * 512 + kw;
    int s1 = nh * 512 + nw;
    float re = 0.25f * (Hr[s0] + Hr[s1]);
    float im = 0.25f * (Hi[s0] - Hi[s1]);
    g_filter[pw * 512 + ph] = make_float2(re * INV_SCALE, im * INV_SCALE);
}

// ---------------------------------------------------------------------------
// Kernel 1: paired forward FFT along W. 64 threads = one FFT pair per block.
// Writes half-spectra into grouped layout: idx = (p>>3)*GRP + h*8 + (p&7).
// ---------------------------------------------------------------------------
__global__ void __launch_bounds__(64) k_fft_rows(const float* __restrict__ x){
    __shared__ float2 sD[PLX];
    __shared__ float2 tws[64];
    int t = threadIdx.x;
    tws[t] = g_tws[t];
    int pair = blockIdx.x;               // 0..32767
    int img  = pair >> 8;
    int h0   = (pair & 255) * 2;
    const float* x0 = x + (size_t)pair * 1024;
    const float* x1 = x0 + 512;

    float2 a[8];
    #pragma unroll
    for (int j = 0; j < 8; ++j) a[j] = make_float2(x0[t + 64*j], x1[t + 64*j]);
    __syncthreads();   // tws ready

    fft512_fwd(a, sD, t, tws);

    __syncthreads();
    #pragma unroll
    for (int q = 0; q < 8; ++q) sD[t + 64*q] = a[q];
    __syncthreads();

    __half2* ib = g_scratch + (size_t)img * IMGS;
    int rr = t >> 3, tp = t & 7;
    #pragma unroll
    for (int q = 0; q < 4; ++q){
        int p = t + 64*q;
        int pm = p ? kmap9(512 - kmap9(p)) : 0;
        float2 A = sD[p];
        float2 B = sD[pm];
        unsigned off = (unsigned)(8*q + rr) * GRP + tp;
        ib[off + h0*8]       = pack_h2(A.x + B.x, A.y - B.y);
        ib[off + (h0+1)*8]   = pack_h2(A.y + B.y, B.x - A.x);
    }
    if (t == 0){   // p = 256, self-mirror: group 32, wi 0
        float2 A = sD[256];
        unsigned off = 32u * GRP;
        ib[off + h0*8]     = pack_h2(2.0f * A.x, 0.0f);
        ib[off + (h0+1)*8] = pack_h2(2.0f * A.y, 0.0f);
    }
}

// ---------------------------------------------------------------------------
// Kernel 2: per image, one group of 8 spectrum columns per block (256 thr).
// Contiguous 16KB uint4 stage-in/out; each 64-thread line runs 2 columns.
// fp16 FFT planes halve shared-memory traffic.
// ---------------------------------------------------------------------------
#define SHP 513   // uint pitch per column in staging buffer (conflict-free)
__global__ void __launch_bounds__(256) k_cols(void){
    __shared__ __half2 sP[4][HPL];
    __shared__ unsigned sH[8 * SHP];
    __shared__ float2 tws[64];
    int tid = threadIdx.x;
    if (tid < 64) tws[tid] = g_tws[tid];

    int img = blockIdx.x / NGRP;
    int g   = blockIdx.x % NGRP;
    uint4* gbase = (uint4*)(g_scratch + (size_t)img * IMGS + (size_t)g * GRP);

    // stage-in: 1024 uint4 = 4096 half2 (full group), perfectly coalesced
    #pragma unroll
    for (int it = 0; it < 4; ++it){
        int idx = it * 256 + tid;        // 0..1023
        uint4 v = gbase[idx];
        int h  = idx >> 1;
        int wb = (idx & 1) * 4;
        sH[(wb+0)*SHP + h] = v.x;
        sH[(wb+1)*SHP + h] = v.y;
        sH[(wb+2)*SHP + h] = v.z;
        sH[(wb+3)*SHP + h] = v.w;
    }
    __syncthreads();

    int line = tid >> 6, t = tid & 63;
    #pragma unroll
    for (int half = 0; half < 2; ++half){
        int wi = line + half * 4;
        float2 a[8];
        #pragma unroll
        for (int j = 0; j < 8; ++j) a[j] = unpack_u(sH[wi*SHP + t + 64*j]);

        fft512_fwd_h(a, sP[line], t, tws);   // first plane write safe: prior
                                             // sync (stage-in / end of half 0)

        int pw = g * 8 + wi; if (pw > 256) pw = 256;
        const float2* frow = g_filter + (size_t)pw * 512 + t;
        #pragma unroll
        for (int q = 0; q < 8; ++q) a[q] = cmul(a[q], frow[64*q]);

        __syncthreads();   // fwd's last plane reads done before inv writes

        fft512_inv_h(a, sP[line], t, tws);

        __syncthreads();   // inv's last plane reads done before next fwd / exit
        #pragma unroll
        for (int j = 0; j < 8; ++j) sH[wi*SHP + t + 64*j] = pack_u(a[j].x, a[j].y);
    }
    __syncthreads();

    // stage-out
    #pragma unroll
    for (int it = 0; it < 4; ++it){
        int idx = it * 256 + tid;
        int h  = idx >> 1;
        int wb = (idx & 1) * 4;
        uint4 v;
        v.x = sH[(wb+0)*SHP + h];
        v.y = sH[(wb+1)*SHP + h];
        v.z = sH[(wb+2)*SHP + h];
        v.w = sH[(wb+3)*SHP + h];
        gbase[idx] = v;
    }
}

// ---------------------------------------------------------------------------
// Kernel 3: paired inverse FFT along W (C2R x2). 64 threads = one pair per block.
// ---------------------------------------------------------------------------
__global__ void __launch_bounds__(64) k_ifft_rows(float* __restrict__ out){
    __shared__ float2 sD[PLX];
    __shared__ float2 tws[64];
    int t = threadIdx.x;
    tws[t] = g_tws[t];
    int pair = blockIdx.x;
    int img  = pair >> 8;
    int h0   = (pair & 255) * 2;
    const __half2* ib = g_scratch + (size_t)img * IMGS;
    int rr = t >> 3, tp = t & 7;

    // stage both half-spectra: S0 at [0..256], S1 at [288..544]
    #pragma unroll
    for (int j = 0; j < 4; ++j){
        int p = t + 64*j;
        unsigned off = (unsigned)(8*j + rr) * GRP + tp;
        sD[p]       = unpack_h2(ib[off + h0*8]);
        sD[288 + p] = unpack_h2(ib[off + (h0+1)*8]);
    }
    if (t == 0){
        unsigned off = 32u * GRP;
        sD[256]       = unpack_h2(ib[off + h0*8]);
        sD[288 + 256] = unpack_h2(ib[off + (h0+1)*8]);
    }
    __syncthreads();

    // build permuted Z in registers:
    // p<=256: Z = S0[p] + i*S1[p];  p>256: Z = conj(S0[ps]) + i*conj(S1[ps])
    float2 a[8];
    #pragma unroll
    for (int q = 0; q < 8; ++q){
        int p = t + 64*q;
        if (p <= 256){
            float2 A = sD[p];
            float2 B = sD[288 + p];
            a[q] = make_float2(A.x - B.y, A.y + B.x);
        } else {
            int ps = kmap9(512 - kmap9(p));   // in [1,255]
            float2 A = sD[ps];
            float2 B = sD[288 + ps];
            a[q] = make_float2(A.x + B.y, B.x - A.y);
        }
    }
    __syncthreads();   // staging reads done before inv FFT reuses plane

    fft512_inv(a, sD, t, tws);

    float* o0 = out + (size_t)pair * 1024;
    float* o1 = o0 + 512;
    #pragma unroll
    for (int j = 0; j < 8; ++j){
        o0[t + 64*j] = a[j].x;
        o1[t + 64*j] = a[j].y;
    }
}

// ---------------------------------------------------------------------------
extern "C" void kernel_launch(void* const* d_in, const int* in_sizes, int n_in,
                              void* d_out, int out_size){
    const float* x  = (const float*)d_in[0];
    const float* Hr = (const float*)d_in[1];
    const float* Hi = (const float*)d_in[2];
    float* out = (float*)d_out;

    k_bake_filter<<<257, 512>>>(Hr, Hi);
    k_fft_rows<<<NROWS / 2, 64>>>(x);
    k_cols<<<NIMG * NGRP, 256>>>();
    k_ifft_rows<<<NROWS / 2, 64>>>(out);
}

// round 12
// speedup vs baseline: 1.1576x; 1.0509x over previous
#include <cuda_runtime.h>
#include <cuda_fp16.h>

#define DIM_H 512
#define NIMG  128
#define NROWS (NIMG * DIM_H)           // 65536 row-lines
#define INV_SCALE (1.0f / (512.0f * 512.0f))
#define HPL 584                         // half2 plane pitch (all kernels)
#define NGRP 33                         // column groups of 8 (257 cols padded to 264)
#define GRP  4096                       // half2 per group = 512*8
#define IMGS (NGRP * GRP)               // half2 per image = 135168

// Scratch: [img][group][h][wi] in fp16 complex, 69 MB. Group = 8 adjacent spectrum cols.
__device__ __half2 g_scratch[(size_t)NIMG * IMGS];
// Baked Hermitianized filter (fp32): [pw 0..256][ph 0..511], scale+untangle folded.
__device__ float2 g_filter[(size_t)257 * 512];
// Baked twiddles: g_tws[k] = exp(-2*pi*i*k/512), k in [0,64)
__device__ float2 g_tws[64];

__device__ __forceinline__ float2 cadd(float2 a, float2 b){ return make_float2(a.x+b.x, a.y+b.y); }
__device__ __forceinline__ float2 csub(float2 a, float2 b){ return make_float2(a.x-b.x, a.y-b.y); }
__device__ __forceinline__ float2 cmul(float2 a, float2 b){
    return make_float2(a.x*b.x - a.y*b.y, a.x*b.y + a.y*b.x);
}
__device__ __forceinline__ float2 cconj(float2 a){ return make_float2(a.x, -a.y); }

__device__ __forceinline__ __half2 pack_h2(float re, float im){ return __floats2half2_rn(re, im); }
__device__ __forceinline__ float2 unpack_h2(__half2 v){ return __half22float2(v); }
__device__ __forceinline__ float2 unpack_u(unsigned u){
    __half2 h = *reinterpret_cast<__half2*>(&u);
    return __half22float2(h);
}
__device__ __forceinline__ unsigned pack_u(float x, float y){
    __half2 h = __floats2half2_rn(x, y);
    return *reinterpret_cast<unsigned*>(&h);
}

// storage-position <-> frequency permutation: swap low two octal digits (involution, keeps bit 8)
__device__ __forceinline__ int kmap9(int p){
    return (p & 448) | ((p & 7) << 3) | ((p >> 3) & 7);
}

// 8-point DFT, natural in/out: out[r] = sum_j in[j] * exp(S*2*pi*i*j*r/8)
template<int S>
__device__ __forceinline__ void dft8(float2* a){
    const float sg = (float)S;
    float2 e0=a[0], e1=a[2], e2=a[4], e3=a[6];
    float2 o0=a[1], o1=a[3], o2=a[5], o3=a[7];
    float2 t0=cadd(e0,e2), t1=csub(e0,e2), t2=cadd(e1,e3), t3=csub(e1,e3);
    float2 t3r = make_float2(-sg*t3.y, sg*t3.x);
    float2 E0=cadd(t0,t2), E2=csub(t0,t2), E1=cadd(t1,t3r), E3=csub(t1,t3r);
    float2 u0=cadd(o0,o2), u1=csub(o0,o2), u2=cadd(o1,o3), u3=csub(o1,o3);
    float2 u3r = make_float2(-sg*u3.y, sg*u3.x);
    float2 O0=cadd(u0,u2), O2=csub(u0,u2), O1=cadd(u1,u3r), O3=csub(u1,u3r);
    const float c = 0.70710678118654752f;
    O1 = make_float2(c*(O1.x - sg*O1.y), c*(sg*O1.x + O1.y));
    O2 = make_float2(-sg*O2.y, sg*O2.x);
    O3 = make_float2(c*(-O3.x - sg*O3.y), c*(sg*O3.x - O3.y));
    a[0]=cadd(E0,O0); a[4]=csub(E0,O0);
    a[1]=cadd(E1,O1); a[5]=csub(E1,O1);
    a[2]=cadd(E2,O2); a[6]=csub(E2,O2);
    a[3]=cadd(E3,O3); a[7]=csub(E3,O3);
}

// Apply w^r to a[r], r=1..7, via binary powering (dep depth 3).
__device__ __forceinline__ void apply7(float2* a, float2 w1){
    float2 w2 = cmul(w1, w1);
    float2 w3 = cmul(w2, w1);
    float2 w4 = cmul(w2, w2);
    float2 w5 = cmul(w3, w2);
    float2 w6 = cmul(w3, w3);
    float2 w7 = cmul(w4, w3);
    a[1] = cmul(a[1], w1); a[2] = cmul(a[2], w2); a[3] = cmul(a[3], w3);
    a[4] = cmul(a[4], w4); a[5] = cmul(a[5], w5); a[6] = cmul(a[6], w6);
    a[7] = cmul(a[7], w7);
}

// ---------- fp16-plane FFTs (all kernels) ----------
// Forward 512-pt FFT. In: a[j] = x[t + 64*j]. Out: a[q] = X[kmap9(t + 64*q)].
__device__ __forceinline__ void fft512_fwd_h(float2* a, __half2* pl, int t,
                                             const float2* tws){
    dft8<-1>(a);
    apply7(a, tws[t]);
    #pragma unroll
    for (int r = 0; r < 8; ++r) pl[r*72 + t] = pack_h2(a[r].x, a[r].y);
    __syncthreads();
    int tp = t & 7, rr = t >> 3;
    #pragma unroll
    for (int j = 0; j < 8; ++j) a[j] = unpack_h2(pl[rr*72 + tp + 8*j]);
    dft8<-1>(a);
    apply7(a, tws[tp*8]);
    __syncthreads();
    #pragma unroll
    for (int r1 = 0; r1 < 8; ++r1) pl[rr*72 + r1*9 + tp] = pack_h2(a[r1].x, a[r1].y);
    __syncthreads();
    #pragma unroll
    for (int k = 0; k < 8; ++k) a[k] = unpack_h2(pl[t*9 + k]);
    dft8<-1>(a);
}

// Inverse (unscaled) 512-pt FFT. In: a[q] = S[kmap9(t + 64*q)]. Out: a[j] = y[t + 64*j].
__device__ __forceinline__ void fft512_inv_h(float2* a, __half2* pl, int t,
                                             const float2* tws){
    dft8<1>(a);
    int tp = t & 7, rr = t >> 3;
    #pragma unroll
    for (int k = 0; k < 8; ++k) pl[t*9 + k] = pack_h2(a[k].x, a[k].y);
    __syncthreads();
    #pragma unroll
    for (int r1 = 0; r1 < 8; ++r1) a[r1] = unpack_h2(pl[rr*72 + r1*9 + tp]);
    apply7(a, cconj(tws[tp*8]));
    dft8<1>(a);
    __syncthreads();
    #pragma unroll
    for (int j = 0; j < 8; ++j) pl[rr*72 + tp + 8*j] = pack_h2(a[j].x, a[j].y);
    __syncthreads();
    #pragma unroll
    for (int r = 0; r < 8; ++r) a[r] = unpack_h2(pl[r*72 + t]);
    apply7(a, cconj(tws[t]));
    dft8<1>(a);
}

// ---------------------------------------------------------------------------
// Kernel 0: bake Hermitianized filter + twiddle table.
// ---------------------------------------------------------------------------
__global__ void k_bake_filter(const float* __restrict__ Hr, const float* __restrict__ Hi){
    int pw = blockIdx.x;          // 0..256
    int ph = threadIdx.x;         // 0..511
    if (pw == 0 && ph < 64){
        float s, c;
        sincosf(-6.283185307179586f * (float)ph / 512.0f, &s, &c);
        g_tws[ph] = make_float2(c, s);
    }
    int kh = kmap9(ph), kw = kmap9(pw);
    int nh = (512 - kh) & 511, nw = (512 - kw) & 511;
    int s0 = kh * 512 + kw;
    int s1 = nh * 512 + nw;
    float re = 0.25f * (Hr[s0] + Hr[s1]);
    float im = 0.25f * (Hi[s0] - Hi[s1]);
    g_filter[pw * 512 + ph] = make_float2(re * INV_SCALE, im * INV_SCALE);
}

// ---------------------------------------------------------------------------
// Kernel 1: paired forward FFT along W. 64 threads = one FFT pair per block.
// fp16 planes + fp16 spectrum staging. Grouped global layout.
// ---------------------------------------------------------------------------
__global__ void __launch_bounds__(64) k_fft_rows(const float* __restrict__ x){
    __shared__ __half2 sP[HPL];
    __shared__ float2 tws[64];
    int t = threadIdx.x;
    tws[t] = g_tws[t];
    int pair = blockIdx.x;               // 0..32767
    int img  = pair >> 8;
    int h0   = (pair & 255) * 2;
    const float* x0 = x + (size_t)pair * 1024;
    const float* x1 = x0 + 512;

    float2 a[8];
    #pragma unroll
    for (int j = 0; j < 8; ++j) a[j] = make_float2(x0[t + 64*j], x1[t + 64*j]);
    __syncthreads();   // tws ready

    fft512_fwd_h(a, sP, t, tws);

    __syncthreads();   // FFT's last plane reads done; plane reusable as staging
    #pragma unroll
    for (int q = 0; q < 8; ++q) sP[t + 64*q] = pack_h2(a[q].x, a[q].y);
    __syncthreads();

    __half2* ib = g_scratch + (size_t)img * IMGS;
    int rr = t >> 3, tp = t & 7;
    #pragma unroll
    for (int q = 0; q < 4; ++q){
        int p = t + 64*q;
        int pm = p ? kmap9(512 - kmap9(p)) : 0;
        float2 A = unpack_h2(sP[p]);
        float2 B = unpack_h2(sP[pm]);
        unsigned off = (unsigned)(8*q + rr) * GRP + tp;
        ib[off + h0*8]       = pack_h2(A.x + B.x, A.y - B.y);
        ib[off + (h0+1)*8]   = pack_h2(A.y + B.y, B.x - A.x);
    }
    if (t == 0){   // p = 256, self-mirror: group 32, wi 0
        float2 A = unpack_h2(sP[256]);
        unsigned off = 32u * GRP;
        ib[off + h0*8]     = pack_h2(2.0f * A.x, 0.0f);
        ib[off + (h0+1)*8] = pack_h2(2.0f * A.y, 0.0f);
    }
}

// ---------------------------------------------------------------------------
// Kernel 2: per image, one group of 8 spectrum columns per block (256 thr).
// Contiguous 16KB uint4 stage-in/out; each 64-thread line runs 2 columns.
// ---------------------------------------------------------------------------
#define SHP 513   // uint pitch per column in staging buffer (conflict-free)
__global__ void __launch_bounds__(256) k_cols(void){
    __shared__ __half2 sP[4][HPL];
    __shared__ unsigned sH[8 * SHP];
    __shared__ float2 tws[64];
    int tid = threadIdx.x;
    if (tid < 64) tws[tid] = g_tws[tid];

    int img = blockIdx.x / NGRP;
    int g   = blockIdx.x % NGRP;
    uint4* gbase = (uint4*)(g_scratch + (size_t)img * IMGS + (size_t)g * GRP);

    // stage-in: 1024 uint4 = 4096 half2 (full group), perfectly coalesced
    #pragma unroll
    for (int it = 0; it < 4; ++it){
        int idx = it * 256 + tid;        // 0..1023
        uint4 v = gbase[idx];
        int h  = idx >> 1;
        int wb = (idx & 1) * 4;
        sH[(wb+0)*SHP + h] = v.x;
        sH[(wb+1)*SHP + h] = v.y;
        sH[(wb+2)*SHP + h] = v.z;
        sH[(wb+3)*SHP + h] = v.w;
    }
    __syncthreads();

    int line = tid >> 6, t = tid & 63;
    #pragma unroll
    for (int half = 0; half < 2; ++half){
        int wi = line + half * 4;
        float2 a[8];
        #pragma unroll
        for (int j = 0; j < 8; ++j) a[j] = unpack_u(sH[wi*SHP + t + 64*j]);

        fft512_fwd_h(a, sP[line], t, tws);   // first plane write safe: prior
                                             // sync (stage-in / end of half 0)

        int pw = g * 8 + wi; if (pw > 256) pw = 256;
        const float2* frow = g_filter + (size_t)pw * 512 + t;
        #pragma unroll
        for (int q = 0; q < 8; ++q) a[q] = cmul(a[q], frow[64*q]);

        __syncthreads();   // fwd's last plane reads done before inv writes

        fft512_inv_h(a, sP[line], t, tws);

        __syncthreads();   // inv's last plane reads done before next fwd / exit
        #pragma unroll
        for (int j = 0; j < 8; ++j) sH[wi*SHP + t + 64*j] = pack_u(a[j].x, a[j].y);
    }
    __syncthreads();

    // stage-out
    #pragma unroll
    for (int it = 0; it < 4; ++it){
        int idx = it * 256 + tid;
        int h  = idx >> 1;
        int wb = (idx & 1) * 4;
        uint4 v;
        v.x = sH[(wb+0)*SHP + h];
        v.y = sH[(wb+1)*SHP + h];
        v.z = sH[(wb+2)*SHP + h];
        v.w = sH[(wb+3)*SHP + h];
        gbase[idx] = v;
    }
}

// ---------------------------------------------------------------------------
// Kernel 3: paired inverse FFT along W (C2R x2). 64 threads = one pair per block.
// fp16 staging (lossless copy of fp16 data) + fp16 planes.
// ---------------------------------------------------------------------------
__global__ void __launch_bounds__(64) k_ifft_rows(float* __restrict__ out){
    __shared__ __half2 sP[HPL];
    __shared__ float2 tws[64];
    int t = threadIdx.x;
    tws[t] = g_tws[t];
    int pair = blockIdx.x;
    int img  = pair >> 8;
    int h0   = (pair & 255) * 2;
    const __half2* ib = g_scratch + (size_t)img * IMGS;
    int rr = t >> 3, tp = t & 7;

    // stage both half-spectra: S0 at [0..256], S1 at [288..544] (raw fp16 copy)
    #pragma unroll
    for (int j = 0; j < 4; ++j){
        int p = t + 64*j;
        unsigned off = (unsigned)(8*j + rr) * GRP + tp;
        sP[p]       = ib[off + h0*8];
        sP[288 + p] = ib[off + (h0+1)*8];
    }
    if (t == 0){
        unsigned off = 32u * GRP;
        sP[256]       = ib[off + h0*8];
        sP[288 + 256] = ib[off + (h0+1)*8];
    }
    __syncthreads();

    // build permuted Z in registers:
    // p<=256: Z = S0[p] + i*S1[p];  p>256: Z = conj(S0[ps]) + i*conj(S1[ps])
    float2 a[8];
    #pragma unroll
    for (int q = 0; q < 8; ++q){
        int p = t + 64*q;
        if (p <= 256){
            float2 A = unpack_h2(sP[p]);
            float2 B = unpack_h2(sP[288 + p]);
            a[q] = make_float2(A.x - B.y, A.y + B.x);
        } else {
            int ps = kmap9(512 - kmap9(p));   // in [1,255]
            float2 A = unpack_h2(sP[ps]);
            float2 B = unpack_h2(sP[288 + ps]);
            a[q] = make_float2(A.x + B.y, B.x - A.y);
        }
    }
    __syncthreads();   // staging reads done before inv FFT reuses plane

    fft512_inv_h(a, sP, t, tws);

    float* o0 = out + (size_t)pair * 1024;
    float* o1 = o0 + 512;
    #pragma unroll
    for (int j = 0; j < 8; ++j){
        o0[t + 64*j] = a[j].x;
        o1[t + 64*j] = a[j].y;
    }
}

// ---------------------------------------------------------------------------
extern "C" void kernel_launch(void* const* d_in, const int* in_sizes, int n_in,
                              void* d_out, int out_size){
    const float* x  = (const float*)d_in[0];
    const float* Hr = (const float*)d_in[1];
    const float* Hi = (const float*)d_in[2];
    float* out = (float*)d_out;

    k_bake_filter<<<257, 512>>>(Hr, Hi);
    k_fft_rows<<<NROWS / 2, 64>>>(x);
    k_cols<<<NIMG * NGRP, 256>>>();
    k_ifft_rows<<<NROWS / 2, 64>>>(out);
}

// round 13
// speedup vs baseline: 1.2543x; 1.0836x over previous
#include <cuda_runtime.h>
#include <cuda_fp16.h>

#define DIM_H 512
#define NIMG  128
#define NROWS (NIMG * DIM_H)           // 65536 row-lines
#define INV_SCALE (1.0f / (512.0f * 512.0f))
#define HPL 584                         // half2 plane pitch (all kernels)
#define NGRP 33                         // column groups of 8 (257 cols padded to 264)
#define GRP  4096                       // half2 per group = 512*8
#define IMGS (NGRP * GRP)               // half2 per image = 135168

// Scratch: [img][group][h][wi] in fp16 complex, 69 MB. Group = 8 adjacent spectrum cols.
__device__ __half2 g_scratch[(size_t)NIMG * IMGS];
// Baked Hermitianized filter (fp32): [pw 0..256][ph 0..511], scale+untangle folded.
__device__ float2 g_filter[(size_t)257 * 512];
// Baked twiddles: g_tws[k] = exp(-2*pi*i*k/512), k in [0,64)
__device__ float2 g_tws[64];

// ---------------- packed f32x2 complex primitives ----------------
typedef unsigned long long u64c;   // one complex: lo = re, hi = im

__device__ __forceinline__ u64c pk2(float x, float y){
    u64c r; asm("mov.b64 %0, {%1, %2};" : "=l"(r) : "f"(x), "f"(y)); return r;
}
__device__ __forceinline__ float2 up2(u64c v){
    float2 r; asm("mov.b64 {%0, %1}, %2;" : "=f"(r.x), "=f"(r.y) : "l"(v)); return r;
}
__device__ __forceinline__ u64c addp(u64c a, u64c b){
    u64c r; asm("add.rn.f32x2 %0, %1, %2;" : "=l"(r) : "l"(a), "l"(b)); return r;
}
__device__ __forceinline__ u64c mulp(u64c a, u64c b){
    u64c r; asm("mul.rn.f32x2 %0, %1, %2;" : "=l"(r) : "l"(a), "l"(b)); return r;
}
__device__ __forceinline__ u64c fmap(u64c a, u64c b, u64c c){
    u64c r; asm("fma.rn.f32x2 %0, %1, %2, %3;" : "=l"(r) : "l"(a), "l"(b), "l"(c)); return r;
}
// a - b, exact (mul by -1 is exact, then .rn add)
__device__ __forceinline__ u64c subp(u64c a, u64c b){
    return fmap(b, pk2(-1.0f, -1.0f), a);
}
// rot<S>(v) = i*S*v
template<int S>
__device__ __forceinline__ u64c rotp(u64c v){
    float2 f = up2(v);
    return (S > 0) ? pk2(-f.y, f.x) : pk2(f.y, -f.x);
}

__device__ __forceinline__ float2 cmul(float2 a, float2 b){
    return make_float2(a.x*b.x - a.y*b.y, a.x*b.y + a.y*b.x);
}
__device__ __forceinline__ float2 cconj(float2 a){ return make_float2(a.x, -a.y); }
// packed * scalar-complex (twiddle/filter application)
__device__ __forceinline__ u64c cmul_ps(u64c a, float2 b){
    float2 f = up2(a);
    return pk2(f.x*b.x - f.y*b.y, f.x*b.y + f.y*b.x);
}

__device__ __forceinline__ __half2 pack_h2(float re, float im){ return __floats2half2_rn(re, im); }
__device__ __forceinline__ float2 unpack_h2(__half2 v){ return __half22float2(v); }
__device__ __forceinline__ float2 unpack_u(unsigned u){
    __half2 h = *reinterpret_cast<__half2*>(&u);
    return __half22float2(h);
}
__device__ __forceinline__ unsigned pack_u(float x, float y){
    __half2 h = __floats2half2_rn(x, y);
    return *reinterpret_cast<unsigned*>(&h);
}

// storage-position <-> frequency permutation: swap low two octal digits (involution, keeps bit 8)
__device__ __forceinline__ int kmap9(int p){
    return (p & 448) | ((p & 7) << 3) | ((p >> 3) & 7);
}

// 8-point DFT, packed, natural in/out: out[r] = sum_j in[j] * exp(S*2*pi*i*j*r/8)
template<int S>
__device__ __forceinline__ void dft8p(u64c* a){
    u64c t0=addp(a[0],a[4]), t1=subp(a[0],a[4]);
    u64c t2=addp(a[2],a[6]), t3=subp(a[2],a[6]);
    u64c t3r=rotp<S>(t3);
    u64c E0=addp(t0,t2), E2=subp(t0,t2), E1=addp(t1,t3r), E3=subp(t1,t3r);
    u64c u0=addp(a[1],a[5]), u1=subp(a[1],a[5]);
    u64c u2=addp(a[3],a[7]), u3=subp(a[3],a[7]);
    u64c u3r=rotp<S>(u3);
    u64c O0=addp(u0,u2), O2=subp(u0,u2), O1=addp(u1,u3r), O3=subp(u1,u3r);
    const float c = 0.70710678118654752f;
    u64c cc = pk2(c, c);
    O1 = mulp(cc, addp(O1, rotp<S>(O1)));          // *(c + i*S*c)
    u64c O2r = rotp<S>(O2);                         // *(i*S)
    O3 = mulp(cc, subp(rotp<S>(O3), O3));           // *(-c + i*S*c)
    a[0]=addp(E0,O0); a[4]=subp(E0,O0);
    a[1]=addp(E1,O1); a[5]=subp(E1,O1);
    a[2]=addp(E2,O2r); a[6]=subp(E2,O2r);
    a[3]=addp(E3,O3); a[7]=subp(E3,O3);
}

// Apply w^r to a[r], r=1..7. Powers scalar (dep depth 3), application packed-scalar.
__device__ __forceinline__ void apply7p(u64c* a, float2 w1){
    float2 w2 = cmul(w1, w1);
    float2 w3 = cmul(w2, w1);
    float2 w4 = cmul(w2, w2);
    float2 w5 = cmul(w3, w2);
    float2 w6 = cmul(w3, w3);
    float2 w7 = cmul(w4, w3);
    a[1]=cmul_ps(a[1],w1); a[2]=cmul_ps(a[2],w2); a[3]=cmul_ps(a[3],w3);
    a[4]=cmul_ps(a[4],w4); a[5]=cmul_ps(a[5],w5); a[6]=cmul_ps(a[6],w6);
    a[7]=cmul_ps(a[7],w7);
}

// ---------- fp16-plane FFTs, packed state ----------
// Forward 512-pt FFT. In: a[j] = x[t + 64*j]. Out: a[q] = X[kmap9(t + 64*q)].
__device__ __forceinline__ void fft512_fwd_h(u64c* a, __half2* pl, int t,
                                             const float2* tws){
    dft8p<-1>(a);
    apply7p(a, tws[t]);
    #pragma unroll
    for (int r = 0; r < 8; ++r){ float2 f = up2(a[r]); pl[r*72 + t] = pack_h2(f.x, f.y); }
    __syncthreads();
    int tp = t & 7, rr = t >> 3;
    #pragma unroll
    for (int j = 0; j < 8; ++j){ float2 f = unpack_h2(pl[rr*72 + tp + 8*j]); a[j] = pk2(f.x, f.y); }
    dft8p<-1>(a);
    apply7p(a, tws[tp*8]);
    __syncthreads();
    #pragma unroll
    for (int r1 = 0; r1 < 8; ++r1){ float2 f = up2(a[r1]); pl[rr*72 + r1*9 + tp] = pack_h2(f.x, f.y); }
    __syncthreads();
    #pragma unroll
    for (int k = 0; k < 8; ++k){ float2 f = unpack_h2(pl[t*9 + k]); a[k] = pk2(f.x, f.y); }
    dft8p<-1>(a);
}

// Inverse (unscaled) 512-pt FFT. In: a[q] = S[kmap9(t + 64*q)]. Out: a[j] = y[t + 64*j].
__device__ __forceinline__ void fft512_inv_h(u64c* a, __half2* pl, int t,
                                             const float2* tws){
    dft8p<1>(a);
    int tp = t & 7, rr = t >> 3;
    #pragma unroll
    for (int k = 0; k < 8; ++k){ float2 f = up2(a[k]); pl[t*9 + k] = pack_h2(f.x, f.y); }
    __syncthreads();
    #pragma unroll
    for (int r1 = 0; r1 < 8; ++r1){ float2 f = unpack_h2(pl[rr*72 + r1*9 + tp]); a[r1] = pk2(f.x, f.y); }
    apply7p(a, cconj(tws[tp*8]));
    dft8p<1>(a);
    __syncthreads();
    #pragma unroll
    for (int j = 0; j < 8; ++j){ float2 f = up2(a[j]); pl[rr*72 + tp + 8*j] = pack_h2(f.x, f.y); }
    __syncthreads();
    #pragma unroll
    for (int r = 0; r < 8; ++r){ float2 f = unpack_h2(pl[r*72 + t]); a[r] = pk2(f.x, f.y); }
    apply7p(a, cconj(tws[t]));
    dft8p<1>(a);
}

// ---------------------------------------------------------------------------
// Kernel 0: bake Hermitianized filter + twiddle table.
// ---------------------------------------------------------------------------
__global__ void k_bake_filter(const float* __restrict__ Hr, const float* __restrict__ Hi){
    int pw = blockIdx.x;          // 0..256
    int ph = threadIdx.x;         // 0..511
    if (pw == 0 && ph < 64){
        float s, c;
        sincosf(-6.283185307179586f * (float)ph / 512.0f, &s, &c);
        g_tws[ph] = make_float2(c, s);
    }
    int kh = kmap9(ph), kw = kmap9(pw);
    int nh = (512 - kh) & 511, nw = (512 - kw) & 511;
    int s0 = kh * 512 + kw;
    int s1 = nh * 512 + nw;
    float re = 0.25f * (Hr[s0] + Hr[s1]);
    float im = 0.25f * (Hi[s0] - Hi[s1]);
    g_filter[pw * 512 + ph] = make_float2(re * INV_SCALE, im * INV_SCALE);
}

// ---------------------------------------------------------------------------
// Kernel 1: paired forward FFT along W. 64 threads = one FFT pair per block.
// ---------------------------------------------------------------------------
__global__ void __launch_bounds__(64) k_fft_rows(const float* __restrict__ x){
    __shared__ __half2 sP[HPL];
    __shared__ float2 tws[64];
    int t = threadIdx.x;
    tws[t] = g_tws[t];
    int pair = blockIdx.x;               // 0..32767
    int img  = pair >> 8;
    int h0   = (pair & 255) * 2;
    const float* x0 = x + (size_t)pair * 1024;
    const float* x1 = x0 + 512;

    u64c a[8];
    #pragma unroll
    for (int j = 0; j < 8; ++j) a[j] = pk2(x0[t + 64*j], x1[t + 64*j]);
    __syncthreads();   // tws ready

    fft512_fwd_h(a, sP, t, tws);

    __syncthreads();   // FFT's last plane reads done; plane reusable as staging
    #pragma unroll
    for (int q = 0; q < 8; ++q){ float2 f = up2(a[q]); sP[t + 64*q] = pack_h2(f.x, f.y); }
    __syncthreads();

    __half2* ib = g_scratch + (size_t)img * IMGS;
    int rr = t >> 3, tp = t & 7;
    #pragma unroll
    for (int q = 0; q < 4; ++q){
        int p = t + 64*q;
        int pm = p ? kmap9(512 - kmap9(p)) : 0;
        float2 A = unpack_h2(sP[p]);
        float2 B = unpack_h2(sP[pm]);
        unsigned off = (unsigned)(8*q + rr) * GRP + tp;
        ib[off + h0*8]       = pack_h2(A.x + B.x, A.y - B.y);
        ib[off + (h0+1)*8]   = pack_h2(A.y + B.y, B.x - A.x);
    }
    if (t == 0){   // p = 256, self-mirror: group 32, wi 0
        float2 A = unpack_h2(sP[256]);
        unsigned off = 32u * GRP;
        ib[off + h0*8]     = pack_h2(2.0f * A.x, 0.0f);
        ib[off + (h0+1)*8] = pack_h2(2.0f * A.y, 0.0f);
    }
}

// ---------------------------------------------------------------------------
// Kernel 2: per image, one group of 8 spectrum columns per block (256 thr).
// ---------------------------------------------------------------------------
#define SHP 513   // uint pitch per column in staging buffer (conflict-free)
__global__ void __launch_bounds__(256) k_cols(void){
    __shared__ __half2 sP[4][HPL];
    __shared__ unsigned sH[8 * SHP];
    __shared__ float2 tws[64];
    int tid = threadIdx.x;
    if (tid < 64) tws[tid] = g_tws[tid];

    int img = blockIdx.x / NGRP;
    int g   = blockIdx.x % NGRP;
    uint4* gbase = (uint4*)(g_scratch + (size_t)img * IMGS + (size_t)g * GRP);

    // stage-in: 1024 uint4 = 4096 half2 (full group), perfectly coalesced
    #pragma unroll
    for (int it = 0; it < 4; ++it){
        int idx = it * 256 + tid;        // 0..1023
        uint4 v = gbase[idx];
        int h  = idx >> 1;
        int wb = (idx & 1) * 4;
        sH[(wb+0)*SHP + h] = v.x;
        sH[(wb+1)*SHP + h] = v.y;
        sH[(wb+2)*SHP + h] = v.z;
        sH[(wb+3)*SHP + h] = v.w;
    }
    __syncthreads();

    int line = tid >> 6, t = tid & 63;
    #pragma unroll
    for (int half = 0; half < 2; ++half){
        int wi = line + half * 4;
        u64c a[8];
        #pragma unroll
        for (int j = 0; j < 8; ++j){
            float2 f = unpack_u(sH[wi*SHP + t + 64*j]);
            a[j] = pk2(f.x, f.y);
        }

        fft512_fwd_h(a, sP[line], t, tws);   // first plane write safe: prior
                                             // sync (stage-in / end of half 0)

        int pw = g * 8 + wi; if (pw > 256) pw = 256;
        const float2* frow = g_filter + (size_t)pw * 512 + t;
        #pragma unroll
        for (int q = 0; q < 8; ++q) a[q] = cmul_ps(a[q], frow[64*q]);

        __syncthreads();   // fwd's last plane reads done before inv writes

        fft512_inv_h(a, sP[line], t, tws);

        __syncthreads();   // inv's last plane reads done before next fwd / exit
        #pragma unroll
        for (int j = 0; j < 8; ++j){
            float2 f = up2(a[j]);
            sH[wi*SHP + t + 64*j] = pack_u(f.x, f.y);
        }
    }
    __syncthreads();

    // stage-out
    #pragma unroll
    for (int it = 0; it < 4; ++it){
        int idx = it * 256 + tid;
        int h  = idx >> 1;
        int wb = (idx & 1) * 4;
        uint4 v;
        v.x = sH[(wb+0)*SHP + h];
        v.y = sH[(wb+1)*SHP + h];
        v.z = sH[(wb+2)*SHP + h];
        v.w = sH[(wb+3)*SHP + h];
        gbase[idx] = v;
    }
}

// ---------------------------------------------------------------------------
// Kernel 3: paired inverse FFT along W (C2R x2). 64 threads = one pair per block.
// a[0..3] built straight from own global loads (no shared read-back).
// ---------------------------------------------------------------------------
__global__ void __launch_bounds__(64) k_ifft_rows(float* __restrict__ out){
    __shared__ __half2 sP[HPL];
    __shared__ float2 tws[64];
    int t = threadIdx.x;
    tws[t] = g_tws[t];
    int pair = blockIdx.x;
    int img  = pair >> 8;
    int h0   = (pair & 255) * 2;
    const __half2* ib = g_scratch + (size_t)img * IMGS;
    int rr = t >> 3, tp = t & 7;

    // load own 4 positions of each half-spectrum; also stage for mirror gathers
    __half2 v0[4], v1[4];
    #pragma unroll
    for (int j = 0; j < 4; ++j){
        int p = t + 64*j;
        unsigned off = (unsigned)(8*j + rr) * GRP + tp;
        v0[j] = ib[off + h0*8];
        v1[j] = ib[off + (h0+1)*8];
        sP[p]       = v0[j];
        sP[288 + p] = v1[j];
    }
    if (t == 0){
        unsigned off = 32u * GRP;
        sP[256]       = ib[off + h0*8];
        sP[288 + 256] = ib[off + (h0+1)*8];
    }
    __syncthreads();

    // build permuted Z:
    // p<=256: Z = S0[p] + i*S1[p];  p>256: Z = conj(S0[ps]) + i*conj(S1[ps])
    u64c a[8];
    #pragma unroll
    for (int q = 0; q < 4; ++q){           // own values, straight from registers
        float2 A = unpack_h2(v0[q]);
        float2 B = unpack_h2(v1[q]);
        a[q] = pk2(A.x - B.y, A.y + B.x);
    }
    #pragma unroll
    for (int q = 4; q < 8; ++q){
        int p = t + 64*q;
        if (p <= 256){                     // only t==0, q==4
            float2 A = unpack_h2(sP[p]);
            float2 B = unpack_h2(sP[288 + p]);
            a[q] = pk2(A.x - B.y, A.y + B.x);
        } else {
            int ps = kmap9(512 - kmap9(p));   // in [1,255]
            float2 A = unpack_h2(sP[ps]);
            float2 B = unpack_h2(sP[288 + ps]);
            a[q] = pk2(A.x + B.y, B.x - A.y);
        }
    }
    __syncthreads();   // staging reads done before inv FFT reuses plane

    fft512_inv_h(a, sP, t, tws);

    float* o0 = out + (size_t)pair * 1024;
    float* o1 = o0 + 512;
    #pragma unroll
    for (int j = 0; j < 8; ++j){
        float2 f = up2(a[j]);
        o0[t + 64*j] = f.x;
        o1[t + 64*j] = f.y;
    }
}

// ---------------------------------------------------------------------------
extern "C" void kernel_launch(void* const* d_in, const int* in_sizes, int n_in,
                              void* d_out, int out_size){
    const float* x  = (const float*)d_in[0];
    const float* Hr = (const float*)d_in[1];
    const float* Hi = (const float*)d_in[2];
    float* out = (float*)d_out;

    k_bake_filter<<<257, 512>>>(Hr, Hi);
    k_fft_rows<<<NROWS / 2, 64>>>(x);
    k_cols<<<NIMG * NGRP, 256>>>();
    k_ifft_rows<<<NROWS / 2, 64>>>(out);
}